// round 10
// baseline (speedup 1.0000x reference)
#include <cuda_runtime.h>

typedef unsigned long long u64;

#define HID 10

struct Params {
    const float* W[9];
    const float* b[9];
};

// Dynamic work-stealing counter (reset by reset_kernel before each run).
__device__ unsigned int g_vb_counter;

// Shared weight stash: weights duplicated into (w,w) float2 so one LDS feeds
// a packed f32x2 FMA; rows 16B-aligned so ulonglong2 reads (LDS.128) fetch
// two duplicated weights per instruction.
struct __align__(16) SW {
    float2 Wh[7][HID][HID];   // layers 2..8 (10 -> 10), duplicated; row = 80B
    float2 bh2[7][HID];       // (b, 0) pre-packed
    float2 W1[2][HID];        // layer 1 (2 -> 10), duplicated
    float2 W9[HID];           // layer 9 (10 -> 1), duplicated
    float  b1[HID];
    float  b9;
};

__device__ __forceinline__ u64 pk2(float lo, float hi) {
    u64 r; asm("mov.b64 %0,{%1,%2};" : "=l"(r) : "f"(lo), "f"(hi)); return r;
}
__device__ __forceinline__ void upk2(u64 v, float& lo, float& hi) {
    asm("mov.b64 {%0,%1},%2;" : "=f"(lo), "=f"(hi) : "l"(v));
}
__device__ __forceinline__ u64 fma2(u64 a, u64 b, u64 c) {
    u64 d; asm("fma.rn.f32x2 %0,%1,%2,%3;" : "=l"(d) : "l"(a), "l"(b), "l"(c)); return d;
}
__device__ __forceinline__ u64 mul2(u64 a, u64 b) {
    u64 d; asm("mul.rn.f32x2 %0,%1,%2;" : "=l"(d) : "l"(a), "l"(b)); return d;
}

// Clamp-free fast tanh: t = 1 - 2/(1 + 2^(2*log2(e)*z)).
// ex2 saturates to +inf / 0 at the extremes, rcp maps those to 0 / 1,
// giving exactly +-1 — NaN-free for all finite z.
__device__ __forceinline__ float tanh_fast(float z) {
    float p = z * 2.8853900817779268f;   // 2 * log2(e)
    float e;
    asm("ex2.approx.f32 %0, %1;" : "=f"(e) : "f"(p));
    float r;
    asm("rcp.approx.f32 %0, %1;" : "=f"(r) : "f"(e + 1.0f));
    return fmaf(-2.0f, r, 1.0f);
}

__device__ __forceinline__ void load_weights(SW& s, const Params& p) {
    int t = threadIdx.x;
    for (int l = 0; l < 7; l++)
        for (int i = t; i < HID * HID; i += blockDim.x) {
            float w = p.W[l + 1][i];
            s.Wh[l][i / HID][i % HID] = make_float2(w, w);
        }
    for (int l = 0; l < 7; l++)
        for (int i = t; i < HID; i += blockDim.x)
            s.bh2[l][i] = make_float2(p.b[l + 1][i], 0.0f);
    for (int i = t; i < 2 * HID; i += blockDim.x) {
        float w = p.W[0][i];
        s.W1[i / HID][i % HID] = make_float2(w, w);
    }
    for (int i = t; i < HID; i += blockDim.x) {
        float w = p.W[8][i];
        s.W9[i] = make_float2(w, w);
    }
    for (int i = t; i < HID; i += blockDim.x) s.b1[i] = p.b[0][i];
    if (t == 0) s.b9 = p.b[8][0];
}

__global__ void reset_kernel() {
    g_vb_counter = 0;
}

// ---------------------------------------------------------------------------
// Persistent fused kernel with dynamic work-stealing over virtual blocks.
// 64 threads/block, 11 blocks/SM (22 warps = +10% vs 128x5 config).
//   vb in [0, nfBlocks): jet path, 1 point/thread, 64 points per vb.
//     2nd-order forward-mode AD: P = (u, u_xx-jet), Q = (u_x, u_t).
//   vb in [nfBlocks, totalVB): forward-only path, 64 points per vb.
// Weights are loaded into shared once per block.
// ---------------------------------------------------------------------------
__global__ void __launch_bounds__(64, 11)
fused_kernel(const float* __restrict__ Xf,
             const float* __restrict__ p0, const float* __restrict__ p1,
             const float* __restrict__ p2,
             Params p, float* __restrict__ out,
             int nf, int n0, int nb)
{
    __shared__ SW s;
    __shared__ int s_vb;
    load_weights(s, p);
    __syncthreads();

    const int nfBlocks = (nf + 63) >> 6;
    const int total    = n0 + 2 * nb;
    const int totalVB  = nfBlocks + ((total + 63) >> 6);

    for (;;) {
        if (threadIdx.x == 0)
            s_vb = (int)atomicAdd(&g_vb_counter, 1u);
        __syncthreads();
        int vb = s_vb;
        if (vb >= totalVB) break;
        __syncthreads();   // protect s_vb before next overwrite

        if (vb >= nfBlocks) {
            // ---------------- forward-only path ----------------
            int i = (vb - nfBlocks) * 64 + threadIdx.x;
            if (i >= total) continue;

            const float* src;
            int loc, off;
            if (i < n0)           { src = p0; loc = i;           off = nf; }
            else if (i < n0 + nb) { src = p1; loc = i - n0;      off = nf + n0; }
            else                  { src = p2; loc = i - n0 - nb; off = nf + n0 + nb; }

            float x  = src[2 * loc + 0];
            float tt = src[2 * loc + 1];

            float h[HID];
            #pragma unroll
            for (int j = 0; j < HID; j++)
                h[j] = tanh_fast(fmaf(x, s.W1[0][j].x, fmaf(tt, s.W1[1][j].x, s.b1[j])));

            #pragma unroll 1
            for (int l = 0; l < 7; l++) {
                float z[HID];
                #pragma unroll
                for (int j = 0; j < HID; j++) z[j] = s.bh2[l][j].x;
                #pragma unroll
                for (int k = 0; k < HID; k++) {
                    float hk = h[k];
                    #pragma unroll
                    for (int j = 0; j < HID; j++)
                        z[j] = fmaf(hk, s.Wh[l][k][j].x, z[j]);
                }
                #pragma unroll
                for (int j = 0; j < HID; j++) h[j] = tanh_fast(z[j]);
            }

            float u = s.b9;
            #pragma unroll
            for (int k = 0; k < HID; k++) u = fmaf(h[k], s.W9[k].x, u);

            out[off + loc] = u;
            continue;
        }

        // ---------------- jet path: 1 point per thread ----------------
        int i = vb * 64 + threadIdx.x;
        int c = min(i, nf - 1);

        float2 xy = reinterpret_cast<const float2*>(Xf)[c];

        u64 P[HID], Q[HID];

        // Layer 1: input (x,t); a_x=(1,0), a_t=(0,1), a_xx=0.
        #pragma unroll
        for (int j = 0; j < HID; j++) {
            float w0 = s.W1[0][j].x;
            float w1 = s.W1[1][j].x;
            float z  = fmaf(xy.x, w0, fmaf(xy.y, w1, s.b1[j]));
            float t  = tanh_fast(z);
            float sv = fmaf(-t, t, 1.0f);
            float q  = w0 * w0;                 // zx^2 (zx = w0, zxx = 0)
            float mt = -2.0f * t;
            P[j] = pk2(t, sv * (mt * q));
            Q[j] = pk2(sv * w0, sv * w1);
        }

        // Hidden layers 2..8 — LDS.128 weight/bias reads (two (w,w) per load)
        #pragma unroll 1
        for (int l = 0; l < 7; l++) {
            u64 zP[HID], zQ[HID];
            const ulonglong2* brow =
                reinterpret_cast<const ulonglong2*>(&s.bh2[l][0]);
            #pragma unroll
            for (int jj = 0; jj < HID / 2; jj++) {
                ulonglong2 bb = brow[jj];     // (b,0),(b,0)
                zP[2*jj]   = bb.x;
                zP[2*jj+1] = bb.y;
                zQ[2*jj]   = 0ull;
                zQ[2*jj+1] = 0ull;
            }
            #pragma unroll
            for (int k = 0; k < HID; k++) {
                u64 Pk = P[k], Qk = Q[k];
                const ulonglong2* wrow =
                    reinterpret_cast<const ulonglong2*>(&s.Wh[l][k][0]);
                #pragma unroll
                for (int jj = 0; jj < HID / 2; jj++) {
                    ulonglong2 w = wrow[jj];  // LDS.128: two duplicated weights
                    zP[2*jj]   = fma2(Pk, w.x, zP[2*jj]);
                    zQ[2*jj]   = fma2(Qk, w.x, zQ[2*jj]);
                    zP[2*jj+1] = fma2(Pk, w.y, zP[2*jj+1]);
                    zQ[2*jj+1] = fma2(Qk, w.y, zQ[2*jj+1]);
                }
            }
            #pragma unroll
            for (int j = 0; j < HID; j++) {
                float z, zxx;  upk2(zP[j], z, zxx);
                float zx, zt;  upk2(zQ[j], zx, zt);
                (void)zt;
                float t  = tanh_fast(z);
                float sv = fmaf(-t, t, 1.0f);
                float q  = zx * zx;
                float mt = -2.0f * t;
                float w2 = fmaf(mt, q, zxx);        // zxx - 2 t zx^2
                P[j] = pk2(t, sv * w2);
                Q[j] = mul2(zQ[j], pk2(sv, sv));
            }
        }

        // Output layer (10 -> 1), linear.
        u64 aP = pk2(s.b9, 0.0f);
        u64 aQ = 0ull;
        #pragma unroll
        for (int kk = 0; kk < HID / 2; kk++) {
            ulonglong2 w =
                reinterpret_cast<const ulonglong2*>(&s.W9[0])[kk];
            aP = fma2(P[2*kk],   w.x, aP);
            aQ = fma2(Q[2*kk],   w.x, aQ);
            aP = fma2(P[2*kk+1], w.y, aP);
            aQ = fma2(Q[2*kk+1], w.y, aQ);
        }
        float u, uxx;  upk2(aP, u, uxx);
        float ux, ut;  upk2(aQ, ux, ut);

        const float nu = 0.0031830988618379067f;   // 0.01 / pi
        float f = fmaf(u, ux, fmaf(-nu, uxx, ut)); // u_t + u*u_x - nu*u_xx

        if (i < nf) {
            int offF = nf + n0 + 2 * nb;
            out[i]               = u;
            out[offF + i]        = f;
            out[offF + nf + i]   = ux;
            out[offF + 2*nf + i] = uxx;
        }
    }
}

// ---------------------------------------------------------------------------
// Output layout (reference tuple order, concatenated):
//   [0, nf) u_pred_f | [nf, +n0) u_pred_0 | [+nb) left | [+nb) right
//   | [+nf) f | [+nf) u_x | [+nf) u_xx
// ---------------------------------------------------------------------------
extern "C" void kernel_launch(void* const* d_in, const int* in_sizes, int n_in,
                              void* d_out, int out_size)
{
    Params p;
    for (int i = 0; i < 9; i++) {
        p.W[i] = (const float*)d_in[4 + 2 * i];
        p.b[i] = (const float*)d_in[5 + 2 * i];
    }
    const float* Xf = (const float*)d_in[0];
    const float* x0 = (const float*)d_in[1];
    const float* xl = (const float*)d_in[2];
    const float* xr = (const float*)d_in[3];

    int nf = in_sizes[0] / 2;
    int n0 = in_sizes[1] / 2;
    int nb = in_sizes[2] / 2;

    float* out = (float*)d_out;

    int nfBlocks  = (nf + 63) / 64;
    int fwdBlocks = (n0 + 2 * nb + 63) / 64;
    int totalVB   = nfBlocks + fwdBlocks;

    // One full wave: 152 SMs (GB300) x 11 blocks/SM.
    int grid = 152 * 11;
    if (grid > totalVB) grid = totalVB;

    reset_kernel<<<1, 1>>>();
    fused_kernel<<<grid, 64>>>(Xf, x0, xl, xr, p, out, nf, n0, nb);
}

// round 11
// speedup vs baseline: 1.3131x; 1.3131x over previous
#include <cuda_runtime.h>

typedef unsigned long long u64;

#define HID 10

struct Params {
    const float* W[9];
    const float* b[9];
};

// Dynamic work-stealing counter (reset by reset_kernel before each run).
__device__ unsigned int g_vb_counter;

// Shared weight stash: weights duplicated into (w,w) float2 so one LDS feeds
// a packed f32x2 FMA; rows 16B-aligned so ulonglong2 reads (LDS.128) fetch
// two duplicated weights per instruction.
struct __align__(16) SW {
    float2 Wh[7][HID][HID];   // layers 2..8 (10 -> 10), duplicated; row = 80B
    float2 bh2[7][HID];       // (b, 0) pre-packed
    float2 W1[2][HID];        // layer 1 (2 -> 10), duplicated
    float2 W9[HID];           // layer 9 (10 -> 1), duplicated
    float  b1[HID];
    float  b9;
};

__device__ __forceinline__ u64 pk2(float lo, float hi) {
    u64 r; asm("mov.b64 %0,{%1,%2};" : "=l"(r) : "f"(lo), "f"(hi)); return r;
}
__device__ __forceinline__ void upk2(u64 v, float& lo, float& hi) {
    asm("mov.b64 {%0,%1},%2;" : "=f"(lo), "=f"(hi) : "l"(v));
}
__device__ __forceinline__ u64 fma2(u64 a, u64 b, u64 c) {
    u64 d; asm("fma.rn.f32x2 %0,%1,%2,%3;" : "=l"(d) : "l"(a), "l"(b), "l"(c)); return d;
}
__device__ __forceinline__ u64 mul2(u64 a, u64 b) {
    u64 d; asm("mul.rn.f32x2 %0,%1,%2;" : "=l"(d) : "l"(a), "l"(b)); return d;
}

// Single-instruction MUFU tanh (sm_90+): 1 op, ~16 cyc, no fma-pipe cost.
__device__ __forceinline__ float tanh_fast(float z) {
    float t;
    asm("tanh.approx.f32 %0, %1;" : "=f"(t) : "f"(z));
    return t;
}

__device__ __forceinline__ void load_weights(SW& s, const Params& p) {
    int t = threadIdx.x;
    for (int l = 0; l < 7; l++)
        for (int i = t; i < HID * HID; i += blockDim.x) {
            float w = p.W[l + 1][i];
            s.Wh[l][i / HID][i % HID] = make_float2(w, w);
        }
    for (int l = 0; l < 7; l++)
        for (int i = t; i < HID; i += blockDim.x)
            s.bh2[l][i] = make_float2(p.b[l + 1][i], 0.0f);
    for (int i = t; i < 2 * HID; i += blockDim.x) {
        float w = p.W[0][i];
        s.W1[i / HID][i % HID] = make_float2(w, w);
    }
    for (int i = t; i < HID; i += blockDim.x) {
        float w = p.W[8][i];
        s.W9[i] = make_float2(w, w);
    }
    for (int i = t; i < HID; i += blockDim.x) s.b1[i] = p.b[0][i];
    if (t == 0) s.b9 = p.b[8][0];
}

__global__ void reset_kernel() {
    g_vb_counter = 0;
}

// ---------------------------------------------------------------------------
// Persistent fused kernel with dynamic work-stealing over virtual blocks:
//   vb in [0, nfBlocks): jet path, 1 point/thread, LDS.128 weight reads.
//     2nd-order forward-mode AD: P = (u, u_xx-jet), Q = (u_x, u_t).
//   vb in [nfBlocks, totalVB): forward-only path (initial/boundary points).
// Weights are loaded into shared once per block.
// ---------------------------------------------------------------------------
__global__ void __launch_bounds__(128, 5)
fused_kernel(const float* __restrict__ Xf,
             const float* __restrict__ p0, const float* __restrict__ p1,
             const float* __restrict__ p2,
             Params p, float* __restrict__ out,
             int nf, int n0, int nb)
{
    __shared__ SW s;
    __shared__ int s_vb;
    load_weights(s, p);
    __syncthreads();

    const int nfBlocks = (nf + 127) >> 7;
    const int total    = n0 + 2 * nb;
    const int totalVB  = nfBlocks + ((total + 127) >> 7);

    for (;;) {
        if (threadIdx.x == 0)
            s_vb = (int)atomicAdd(&g_vb_counter, 1u);
        __syncthreads();
        int vb = s_vb;
        if (vb >= totalVB) break;
        __syncthreads();   // protect s_vb before next overwrite

        if (vb >= nfBlocks) {
            // ---------------- forward-only path ----------------
            int i = (vb - nfBlocks) * 128 + threadIdx.x;
            if (i >= total) continue;

            const float* src;
            int loc, off;
            if (i < n0)           { src = p0; loc = i;           off = nf; }
            else if (i < n0 + nb) { src = p1; loc = i - n0;      off = nf + n0; }
            else                  { src = p2; loc = i - n0 - nb; off = nf + n0 + nb; }

            float x  = src[2 * loc + 0];
            float tt = src[2 * loc + 1];

            float h[HID];
            #pragma unroll
            for (int j = 0; j < HID; j++)
                h[j] = tanh_fast(fmaf(x, s.W1[0][j].x, fmaf(tt, s.W1[1][j].x, s.b1[j])));

            #pragma unroll 1
            for (int l = 0; l < 7; l++) {
                float z[HID];
                #pragma unroll
                for (int j = 0; j < HID; j++) z[j] = s.bh2[l][j].x;
                #pragma unroll
                for (int k = 0; k < HID; k++) {
                    float hk = h[k];
                    #pragma unroll
                    for (int j = 0; j < HID; j++)
                        z[j] = fmaf(hk, s.Wh[l][k][j].x, z[j]);
                }
                #pragma unroll
                for (int j = 0; j < HID; j++) h[j] = tanh_fast(z[j]);
            }

            float u = s.b9;
            #pragma unroll
            for (int k = 0; k < HID; k++) u = fmaf(h[k], s.W9[k].x, u);

            out[off + loc] = u;
            continue;
        }

        // ---------------- jet path: 1 point per thread ----------------
        int i = vb * 128 + threadIdx.x;
        int c = min(i, nf - 1);

        float2 xy = reinterpret_cast<const float2*>(Xf)[c];

        u64 P[HID], Q[HID];

        // Layer 1: input (x,t); a_x=(1,0), a_t=(0,1), a_xx=0.
        #pragma unroll
        for (int j = 0; j < HID; j++) {
            float w0 = s.W1[0][j].x;
            float w1 = s.W1[1][j].x;
            float z  = fmaf(xy.x, w0, fmaf(xy.y, w1, s.b1[j]));
            float t  = tanh_fast(z);
            float sv = fmaf(-t, t, 1.0f);
            P[j] = pk2(t, -2.0f * t * sv * w0 * w0);   // zxx = 0, zx = w0
            Q[j] = pk2(sv * w0, sv * w1);
        }

        // Hidden layers 2..8 — LDS.128 weight/bias reads (two (w,w) per load)
        #pragma unroll 1
        for (int l = 0; l < 7; l++) {
            u64 zP[HID], zQ[HID];
            const ulonglong2* brow =
                reinterpret_cast<const ulonglong2*>(&s.bh2[l][0]);
            #pragma unroll
            for (int jj = 0; jj < HID / 2; jj++) {
                ulonglong2 bb = brow[jj];     // (b,0),(b,0)
                zP[2*jj]   = bb.x;
                zP[2*jj+1] = bb.y;
                zQ[2*jj]   = 0ull;
                zQ[2*jj+1] = 0ull;
            }
            #pragma unroll
            for (int k = 0; k < HID; k++) {
                u64 Pk = P[k], Qk = Q[k];
                const ulonglong2* wrow =
                    reinterpret_cast<const ulonglong2*>(&s.Wh[l][k][0]);
                #pragma unroll
                for (int jj = 0; jj < HID / 2; jj++) {
                    ulonglong2 w = wrow[jj];  // LDS.128: two duplicated weights
                    zP[2*jj]   = fma2(Pk, w.x, zP[2*jj]);
                    zQ[2*jj]   = fma2(Qk, w.x, zQ[2*jj]);
                    zP[2*jj+1] = fma2(Pk, w.y, zP[2*jj+1]);
                    zQ[2*jj+1] = fma2(Qk, w.y, zQ[2*jj+1]);
                }
            }
            #pragma unroll
            for (int j = 0; j < HID; j++) {
                float z, zxx;  upk2(zP[j], z, zxx);
                float zx, zt;  upk2(zQ[j], zx, zt);
                (void)zt;
                float t  = tanh_fast(z);
                float sv = fmaf(-t, t, 1.0f);
                P[j] = pk2(t, fmaf(sv, zxx, -2.0f * t * sv * zx * zx));
                Q[j] = mul2(zQ[j], pk2(sv, sv));
            }
        }

        // Output layer (10 -> 1), linear.
        u64 aP = pk2(s.b9, 0.0f);
        u64 aQ = 0ull;
        #pragma unroll
        for (int kk = 0; kk < HID / 2; kk++) {
            ulonglong2 w =
                reinterpret_cast<const ulonglong2*>(&s.W9[0])[kk];
            aP = fma2(P[2*kk],   w.x, aP);
            aQ = fma2(Q[2*kk],   w.x, aQ);
            aP = fma2(P[2*kk+1], w.y, aP);
            aQ = fma2(Q[2*kk+1], w.y, aQ);
        }
        float u, uxx;  upk2(aP, u, uxx);
        float ux, ut;  upk2(aQ, ux, ut);

        const float nu = 0.0031830988618379067f;   // 0.01 / pi
        float f = fmaf(u, ux, fmaf(-nu, uxx, ut)); // u_t + u*u_x - nu*u_xx

        if (i < nf) {
            int offF = nf + n0 + 2 * nb;
            out[i]               = u;
            out[offF + i]        = f;
            out[offF + nf + i]   = ux;
            out[offF + 2*nf + i] = uxx;
        }
    }
}

// ---------------------------------------------------------------------------
// Output layout (reference tuple order, concatenated):
//   [0, nf) u_pred_f | [nf, +n0) u_pred_0 | [+nb) left | [+nb) right
//   | [+nf) f | [+nf) u_x | [+nf) u_xx
// ---------------------------------------------------------------------------
extern "C" void kernel_launch(void* const* d_in, const int* in_sizes, int n_in,
                              void* d_out, int out_size)
{
    Params p;
    for (int i = 0; i < 9; i++) {
        p.W[i] = (const float*)d_in[4 + 2 * i];
        p.b[i] = (const float*)d_in[5 + 2 * i];
    }
    const float* Xf = (const float*)d_in[0];
    const float* x0 = (const float*)d_in[1];
    const float* xl = (const float*)d_in[2];
    const float* xr = (const float*)d_in[3];

    int nf = in_sizes[0] / 2;
    int n0 = in_sizes[1] / 2;
    int nb = in_sizes[2] / 2;

    float* out = (float*)d_out;

    int nfBlocks  = (nf + 127) / 128;
    int fwdBlocks = (n0 + 2 * nb + 127) / 128;
    int totalVB   = nfBlocks + fwdBlocks;

    // One full wave: 152 SMs (GB300) x 5 blocks/SM.
    int grid = 152 * 5;
    if (grid > totalVB) grid = totalVB;

    reset_kernel<<<1, 1>>>();
    fused_kernel<<<grid, 128>>>(Xf, x0, xl, xr, p, out, nf, n0, nb);
}

// round 12
// speedup vs baseline: 1.3549x; 1.0318x over previous
#include <cuda_runtime.h>

typedef unsigned long long u64;

#define HID 10

struct Params {
    const float* W[9];
    const float* b[9];
};

// Dynamic work-stealing counter (reset by reset_kernel before each run).
__device__ unsigned int g_vb_counter;

// Shared weight stash: weights duplicated into (w,w) float2 so one LDS.64
// broadcast feeds packed f32x2 FMAs (for TWO points each: 4 fma2 per load).
struct __align__(16) SW {
    float2 Wh[7][HID][HID];   // layers 2..8 (10 -> 10), duplicated
    float2 bh2[7][HID];       // (b, 0) pre-packed
    float2 W1[2][HID];        // layer 1 (2 -> 10), duplicated
    float2 W9[HID];           // layer 9 (10 -> 1), duplicated
    float  b1[HID];
    float  b9;
};

__device__ __forceinline__ u64 pk2(float lo, float hi) {
    u64 r; asm("mov.b64 %0,{%1,%2};" : "=l"(r) : "f"(lo), "f"(hi)); return r;
}
__device__ __forceinline__ void upk2(u64 v, float& lo, float& hi) {
    asm("mov.b64 {%0,%1},%2;" : "=f"(lo), "=f"(hi) : "l"(v));
}
__device__ __forceinline__ u64 fma2(u64 a, u64 b, u64 c) {
    u64 d; asm("fma.rn.f32x2 %0,%1,%2,%3;" : "=l"(d) : "l"(a), "l"(b), "l"(c)); return d;
}
__device__ __forceinline__ u64 mul2(u64 a, u64 b) {
    u64 d; asm("mul.rn.f32x2 %0,%1,%2;" : "=l"(d) : "l"(a), "l"(b)); return d;
}

// Single-instruction MUFU tanh (sm_90+): 1 op, ~16 cyc, no fma-pipe cost.
__device__ __forceinline__ float tanh_fast(float z) {
    float t;
    asm("tanh.approx.f32 %0, %1;" : "=f"(t) : "f"(z));
    return t;
}

__device__ __forceinline__ void load_weights(SW& s, const Params& p) {
    int t = threadIdx.x;
    for (int l = 0; l < 7; l++)
        for (int i = t; i < HID * HID; i += blockDim.x) {
            float w = p.W[l + 1][i];
            s.Wh[l][i / HID][i % HID] = make_float2(w, w);
        }
    for (int l = 0; l < 7; l++)
        for (int i = t; i < HID; i += blockDim.x)
            s.bh2[l][i] = make_float2(p.b[l + 1][i], 0.0f);
    for (int i = t; i < 2 * HID; i += blockDim.x) {
        float w = p.W[0][i];
        s.W1[i / HID][i % HID] = make_float2(w, w);
    }
    for (int i = t; i < HID; i += blockDim.x) {
        float w = p.W[8][i];
        s.W9[i] = make_float2(w, w);
    }
    for (int i = t; i < HID; i += blockDim.x) s.b1[i] = p.b[0][i];
    if (t == 0) s.b9 = p.b[8][0];
}

__global__ void reset_kernel() {
    g_vb_counter = 0;
}

// ---------------------------------------------------------------------------
// Persistent fused kernel with dynamic work-stealing over virtual blocks.
//   vb in [0, nfBlocks): jet path, 2 points/thread (256 points per vb).
//     2nd-order forward-mode AD: P = (u, u_xx-jet), Q = (u_x, u_t).
//   vb in [nfBlocks, totalVB): forward-only path, 128 points per vb.
// Weights are loaded into shared once per block.
// ---------------------------------------------------------------------------
__global__ void __launch_bounds__(128, 3)
fused_kernel(const float* __restrict__ Xf,
             const float* __restrict__ p0, const float* __restrict__ p1,
             const float* __restrict__ p2,
             Params p, float* __restrict__ out,
             int nf, int n0, int nb)
{
    __shared__ SW s;
    __shared__ int s_vb;
    load_weights(s, p);
    __syncthreads();

    const int nfBlocks = (nf + 255) >> 8;
    const int total    = n0 + 2 * nb;
    const int totalVB  = nfBlocks + ((total + 127) >> 7);

    for (;;) {
        if (threadIdx.x == 0)
            s_vb = (int)atomicAdd(&g_vb_counter, 1u);
        __syncthreads();
        int vb = s_vb;
        if (vb >= totalVB) break;
        __syncthreads();   // protect s_vb before next overwrite

        if (vb >= nfBlocks) {
            // ---------------- forward-only path ----------------
            int i = (vb - nfBlocks) * 128 + threadIdx.x;
            if (i >= total) continue;

            const float* src;
            int loc, off;
            if (i < n0)           { src = p0; loc = i;           off = nf; }
            else if (i < n0 + nb) { src = p1; loc = i - n0;      off = nf + n0; }
            else                  { src = p2; loc = i - n0 - nb; off = nf + n0 + nb; }

            float x  = src[2 * loc + 0];
            float tt = src[2 * loc + 1];

            float h[HID];
            #pragma unroll
            for (int j = 0; j < HID; j++)
                h[j] = tanh_fast(fmaf(x, s.W1[0][j].x, fmaf(tt, s.W1[1][j].x, s.b1[j])));

            #pragma unroll 1
            for (int l = 0; l < 7; l++) {
                float z[HID];
                #pragma unroll
                for (int j = 0; j < HID; j++) z[j] = s.bh2[l][j].x;
                #pragma unroll
                for (int k = 0; k < HID; k++) {
                    float hk = h[k];
                    #pragma unroll
                    for (int j = 0; j < HID; j++)
                        z[j] = fmaf(hk, s.Wh[l][k][j].x, z[j]);
                }
                #pragma unroll
                for (int j = 0; j < HID; j++) h[j] = tanh_fast(z[j]);
            }

            float u = s.b9;
            #pragma unroll
            for (int k = 0; k < HID; k++) u = fmaf(h[k], s.W9[k].x, u);

            out[off + loc] = u;
            continue;
        }

        // ---------------- jet path: 2 points per thread ----------------
        int i0 = vb * 256 + threadIdx.x;
        int i1 = i0 + 128;
        int c0 = min(i0, nf - 1);
        int c1 = min(i1, nf - 1);

        float2 xy0 = reinterpret_cast<const float2*>(Xf)[c0];
        float2 xy1 = reinterpret_cast<const float2*>(Xf)[c1];

        u64 P0[HID], Q0[HID], P1[HID], Q1[HID];

        // Layer 1: input (x,t); a_x=(1,0), a_t=(0,1), a_xx=0.
        #pragma unroll
        for (int j = 0; j < HID; j++) {
            float w0 = s.W1[0][j].x;
            float w1 = s.W1[1][j].x;
            float b  = s.b1[j];

            float z0  = fmaf(xy0.x, w0, fmaf(xy0.y, w1, b));
            float t0  = tanh_fast(z0);
            float sv0 = fmaf(-t0, t0, 1.0f);
            P0[j] = pk2(t0, -2.0f * t0 * sv0 * w0 * w0);
            Q0[j] = pk2(sv0 * w0, sv0 * w1);

            float z1  = fmaf(xy1.x, w0, fmaf(xy1.y, w1, b));
            float t1  = tanh_fast(z1);
            float sv1 = fmaf(-t1, t1, 1.0f);
            P1[j] = pk2(t1, -2.0f * t1 * sv1 * w0 * w0);
            Q1[j] = pk2(sv1 * w0, sv1 * w1);
        }

        // Hidden layers 2..8 — one (w,w) LDS feeds 4 fma2 (both points).
        #pragma unroll 1
        for (int l = 0; l < 7; l++) {
            u64 zP0[HID], zQ0[HID], zP1[HID], zQ1[HID];
            #pragma unroll
            for (int j = 0; j < HID; j++) {
                u64 bz = *reinterpret_cast<const u64*>(&s.bh2[l][j]);
                zP0[j] = bz; zP1[j] = bz;
                zQ0[j] = 0ull; zQ1[j] = 0ull;
            }
            #pragma unroll
            for (int k = 0; k < HID; k++) {
                u64 a0 = P0[k], q0 = Q0[k];
                u64 a1 = P1[k], q1 = Q1[k];
                #pragma unroll
                for (int j = 0; j < HID; j++) {
                    u64 w = *reinterpret_cast<const u64*>(&s.Wh[l][k][j]);
                    zP0[j] = fma2(a0, w, zP0[j]);
                    zQ0[j] = fma2(q0, w, zQ0[j]);
                    zP1[j] = fma2(a1, w, zP1[j]);
                    zQ1[j] = fma2(q1, w, zQ1[j]);
                }
            }
            #pragma unroll
            for (int j = 0; j < HID; j++) {
                float z0, zxx0, zx0, zt0;
                upk2(zP0[j], z0, zxx0); upk2(zQ0[j], zx0, zt0);
                float t0  = tanh_fast(z0);
                float sv0 = fmaf(-t0, t0, 1.0f);
                P0[j] = pk2(t0, fmaf(sv0, zxx0, -2.0f * t0 * sv0 * zx0 * zx0));
                Q0[j] = mul2(zQ0[j], pk2(sv0, sv0));

                float z1, zxx1, zx1, zt1;
                upk2(zP1[j], z1, zxx1); upk2(zQ1[j], zx1, zt1);
                float t1  = tanh_fast(z1);
                float sv1 = fmaf(-t1, t1, 1.0f);
                P1[j] = pk2(t1, fmaf(sv1, zxx1, -2.0f * t1 * sv1 * zx1 * zx1));
                Q1[j] = mul2(zQ1[j], pk2(sv1, sv1));
            }
        }

        // Output layer (10 -> 1), linear.
        u64 aP0 = pk2(s.b9, 0.0f), aQ0 = 0ull;
        u64 aP1 = aP0,             aQ1 = 0ull;
        #pragma unroll
        for (int k = 0; k < HID; k++) {
            u64 w = *reinterpret_cast<const u64*>(&s.W9[k]);
            aP0 = fma2(P0[k], w, aP0);
            aQ0 = fma2(Q0[k], w, aQ0);
            aP1 = fma2(P1[k], w, aP1);
            aQ1 = fma2(Q1[k], w, aQ1);
        }

        const float nu = 0.0031830988618379067f;   // 0.01 / pi

        float u0, uxx0, ux0, ut0;
        upk2(aP0, u0, uxx0); upk2(aQ0, ux0, ut0);
        float f0 = fmaf(u0, ux0, fmaf(-nu, uxx0, ut0));

        float u1, uxx1, ux1, ut1;
        upk2(aP1, u1, uxx1); upk2(aQ1, ux1, ut1);
        float f1 = fmaf(u1, ux1, fmaf(-nu, uxx1, ut1));

        int offF = nf + n0 + 2 * nb;
        if (i0 < nf) {
            out[i0]               = u0;
            out[offF + i0]        = f0;
            out[offF + nf + i0]   = ux0;
            out[offF + 2*nf + i0] = uxx0;
        }
        if (i1 < nf) {
            out[i1]               = u1;
            out[offF + i1]        = f1;
            out[offF + nf + i1]   = ux1;
            out[offF + 2*nf + i1] = uxx1;
        }
    }
}

// ---------------------------------------------------------------------------
// Output layout (reference tuple order, concatenated):
//   [0, nf) u_pred_f | [nf, +n0) u_pred_0 | [+nb) left | [+nb) right
//   | [+nf) f | [+nf) u_x | [+nf) u_xx
// ---------------------------------------------------------------------------
extern "C" void kernel_launch(void* const* d_in, const int* in_sizes, int n_in,
                              void* d_out, int out_size)
{
    Params p;
    for (int i = 0; i < 9; i++) {
        p.W[i] = (const float*)d_in[4 + 2 * i];
        p.b[i] = (const float*)d_in[5 + 2 * i];
    }
    const float* Xf = (const float*)d_in[0];
    const float* x0 = (const float*)d_in[1];
    const float* xl = (const float*)d_in[2];
    const float* xr = (const float*)d_in[3];

    int nf = in_sizes[0] / 2;
    int n0 = in_sizes[1] / 2;
    int nb = in_sizes[2] / 2;

    float* out = (float*)d_out;

    int nfBlocks  = (nf + 255) / 256;
    int fwdBlocks = (n0 + 2 * nb + 127) / 128;
    int totalVB   = nfBlocks + fwdBlocks;

    // One full wave: 152 SMs (GB300) x 3 blocks/SM.
    int grid = 152 * 3;
    if (grid > totalVB) grid = totalVB;

    reset_kernel<<<1, 1>>>();
    fused_kernel<<<grid, 128>>>(Xf, x0, xl, xr, p, out, nf, n0, nb);
}

// round 13
// speedup vs baseline: 1.4058x; 1.0376x over previous
#include <cuda_runtime.h>

typedef unsigned long long u64;

#define HID 10

struct Params {
    const float* W[9];
    const float* b[9];
};

// Dynamic work-stealing counter (reset by reset_kernel before each run).
__device__ unsigned int g_vb_counter;

// Shared weight stash: weights duplicated into (w,w) float2 so one LDS.64
// broadcast feeds a packed-across-points f32x2 FMA (4 fma2 per load).
struct __align__(16) SW {
    float2 Wh[7][HID][HID];   // layers 2..8 (10 -> 10), duplicated
    float2 bh2[7][HID];       // (b, b) pre-packed (both points share bias)
    float2 W1[2][HID];        // layer 1 (2 -> 10), duplicated
    float2 W9[HID];           // layer 9 (10 -> 1), duplicated
    float2 b9_2;              // (b9, b9)
    float  b1[HID];
    float  b9;
};

__device__ __forceinline__ u64 pk2(float lo, float hi) {
    u64 r; asm("mov.b64 %0,{%1,%2};" : "=l"(r) : "f"(lo), "f"(hi)); return r;
}
__device__ __forceinline__ void upk2(u64 v, float& lo, float& hi) {
    asm("mov.b64 {%0,%1},%2;" : "=f"(lo), "=f"(hi) : "l"(v));
}
__device__ __forceinline__ u64 fma2(u64 a, u64 b, u64 c) {
    u64 d; asm("fma.rn.f32x2 %0,%1,%2,%3;" : "=l"(d) : "l"(a), "l"(b), "l"(c)); return d;
}
__device__ __forceinline__ u64 mul2(u64 a, u64 b) {
    u64 d; asm("mul.rn.f32x2 %0,%1,%2;" : "=l"(d) : "l"(a), "l"(b)); return d;
}

// Single-instruction MUFU tanh (sm_90+): 1 op, ~16 cyc, no fma-pipe cost.
__device__ __forceinline__ float tanh_fast(float z) {
    float t;
    asm("tanh.approx.f32 %0, %1;" : "=f"(t) : "f"(z));
    return t;
}

__device__ __forceinline__ void load_weights(SW& s, const Params& p) {
    int t = threadIdx.x;
    for (int l = 0; l < 7; l++)
        for (int i = t; i < HID * HID; i += blockDim.x) {
            float w = p.W[l + 1][i];
            s.Wh[l][i / HID][i % HID] = make_float2(w, w);
        }
    for (int l = 0; l < 7; l++)
        for (int i = t; i < HID; i += blockDim.x) {
            float b = p.b[l + 1][i];
            s.bh2[l][i] = make_float2(b, b);
        }
    for (int i = t; i < 2 * HID; i += blockDim.x) {
        float w = p.W[0][i];
        s.W1[i / HID][i % HID] = make_float2(w, w);
    }
    for (int i = t; i < HID; i += blockDim.x) {
        float w = p.W[8][i];
        s.W9[i] = make_float2(w, w);
    }
    for (int i = t; i < HID; i += blockDim.x) s.b1[i] = p.b[0][i];
    if (t == 0) {
        float b9 = p.b[8][0];
        s.b9   = b9;
        s.b9_2 = make_float2(b9, b9);
    }
}

__global__ void reset_kernel() {
    g_vb_counter = 0;
}

// ---------------------------------------------------------------------------
// Persistent fused kernel with dynamic work-stealing over virtual blocks.
//   vb in [0, nfBlocks): jet path, 2 points/thread, ACROSS-POINT packing:
//     every jet component is an f32x2 over (point0, point1):
//       T = tanh vals, X = du/dx jet, Tt = du/dt jet, XX = d2u/dx2 jet.
//     Activation math is fully packed; only tanh unpacks to scalars.
//   vb in [nfBlocks, totalVB): forward-only path, 128 points per vb.
// ---------------------------------------------------------------------------
__global__ void __launch_bounds__(128, 3)
fused_kernel(const float* __restrict__ Xf,
             const float* __restrict__ p0, const float* __restrict__ p1,
             const float* __restrict__ p2,
             Params p, float* __restrict__ out,
             int nf, int n0, int nb)
{
    __shared__ SW s;
    __shared__ int s_vb;
    load_weights(s, p);
    __syncthreads();

    const int nfBlocks = (nf + 255) >> 8;
    const int total    = n0 + 2 * nb;
    const int totalVB  = nfBlocks + ((total + 127) >> 7);

    const u64 ONE  = pk2(1.0f, 1.0f);
    const u64 NEG1 = pk2(-1.0f, -1.0f);
    const u64 NEG2 = pk2(-2.0f, -2.0f);

    for (;;) {
        if (threadIdx.x == 0)
            s_vb = (int)atomicAdd(&g_vb_counter, 1u);
        __syncthreads();
        int vb = s_vb;
        if (vb >= totalVB) break;
        __syncthreads();   // protect s_vb before next overwrite

        if (vb >= nfBlocks) {
            // ---------------- forward-only path ----------------
            int i = (vb - nfBlocks) * 128 + threadIdx.x;
            if (i >= total) continue;

            const float* src;
            int loc, off;
            if (i < n0)           { src = p0; loc = i;           off = nf; }
            else if (i < n0 + nb) { src = p1; loc = i - n0;      off = nf + n0; }
            else                  { src = p2; loc = i - n0 - nb; off = nf + n0 + nb; }

            float x  = src[2 * loc + 0];
            float tt = src[2 * loc + 1];

            float h[HID];
            #pragma unroll
            for (int j = 0; j < HID; j++)
                h[j] = tanh_fast(fmaf(x, s.W1[0][j].x, fmaf(tt, s.W1[1][j].x, s.b1[j])));

            #pragma unroll 1
            for (int l = 0; l < 7; l++) {
                float z[HID];
                #pragma unroll
                for (int j = 0; j < HID; j++) z[j] = s.bh2[l][j].x;
                #pragma unroll
                for (int k = 0; k < HID; k++) {
                    float hk = h[k];
                    #pragma unroll
                    for (int j = 0; j < HID; j++)
                        z[j] = fmaf(hk, s.Wh[l][k][j].x, z[j]);
                }
                #pragma unroll
                for (int j = 0; j < HID; j++) h[j] = tanh_fast(z[j]);
            }

            float u = s.b9;
            #pragma unroll
            for (int k = 0; k < HID; k++) u = fmaf(h[k], s.W9[k].x, u);

            out[off + loc] = u;
            continue;
        }

        // ---------------- jet path: 2 points per thread ----------------
        int i0 = vb * 256 + threadIdx.x;
        int i1 = i0 + 128;
        int c0 = min(i0, nf - 1);
        int c1 = min(i1, nf - 1);

        float2 xy0 = reinterpret_cast<const float2*>(Xf)[c0];
        float2 xy1 = reinterpret_cast<const float2*>(Xf)[c1];

        // Packed-across-points jet state.
        u64 T[HID], X[HID], Tt[HID], XX[HID];

        // Layer 1: z = w0*x + w1*t + b; zx = w0, zt = w1, zxx = 0.
        #pragma unroll
        for (int j = 0; j < HID; j++) {
            float w0 = s.W1[0][j].x;
            float w1 = s.W1[1][j].x;
            float b  = s.b1[j];
            float z0 = fmaf(xy0.x, w0, fmaf(xy0.y, w1, b));
            float z1 = fmaf(xy1.x, w0, fmaf(xy1.y, w1, b));
            u64 Tn  = pk2(tanh_fast(z0), tanh_fast(z1));
            u64 T2  = mul2(Tn, Tn);
            u64 SV  = fma2(T2, NEG1, ONE);              // 1 - t^2
            u64 W0d = *reinterpret_cast<const u64*>(&s.W1[0][j]);
            u64 W1d = *reinterpret_cast<const u64*>(&s.W1[1][j]);
            u64 W02 = mul2(W0d, W0d);                   // zx^2
            u64 G   = mul2(Tn, W02);
            u64 H   = mul2(G, NEG2);                    // -2 t zx^2  (zxx=0)
            T[j]  = Tn;
            X[j]  = mul2(SV, W0d);
            Tt[j] = mul2(SV, W1d);
            XX[j] = mul2(SV, H);
        }

        // Hidden layers 2..8
        #pragma unroll 1
        for (int l = 0; l < 7; l++) {
            u64 Z[HID], ZX[HID], ZT[HID], ZXX[HID];
            #pragma unroll
            for (int j = 0; j < HID; j++) {
                Z[j]   = *reinterpret_cast<const u64*>(&s.bh2[l][j]);  // (b,b)
                ZX[j]  = 0ull;
                ZT[j]  = 0ull;
                ZXX[j] = 0ull;
            }
            #pragma unroll
            for (int k = 0; k < HID; k++) {
                u64 Tk = T[k], Xk = X[k], Ttk = Tt[k], XXk = XX[k];
                #pragma unroll
                for (int j = 0; j < HID; j++) {
                    u64 w = *reinterpret_cast<const u64*>(&s.Wh[l][k][j]);
                    Z[j]   = fma2(Tk,  w, Z[j]);
                    ZX[j]  = fma2(Xk,  w, ZX[j]);
                    ZT[j]  = fma2(Ttk, w, ZT[j]);
                    ZXX[j] = fma2(XXk, w, ZXX[j]);
                }
            }
            #pragma unroll
            for (int j = 0; j < HID; j++) {
                float z0, z1;  upk2(Z[j], z0, z1);
                u64 Tn  = pk2(tanh_fast(z0), tanh_fast(z1));
                u64 T2  = mul2(Tn, Tn);
                u64 SV  = fma2(T2, NEG1, ONE);          // 1 - t^2
                u64 ZX2 = mul2(ZX[j], ZX[j]);
                u64 G   = mul2(Tn, ZX2);
                u64 H   = fma2(G, NEG2, ZXX[j]);        // zxx - 2 t zx^2
                T[j]  = Tn;
                XX[j] = mul2(SV, H);
                X[j]  = mul2(SV, ZX[j]);
                Tt[j] = mul2(SV, ZT[j]);
            }
        }

        // Output layer (10 -> 1), linear; fully packed.
        u64 U   = *reinterpret_cast<const u64*>(&s.b9_2);
        u64 UX  = 0ull, UT = 0ull, UXX = 0ull;
        #pragma unroll
        for (int k = 0; k < HID; k++) {
            u64 w = *reinterpret_cast<const u64*>(&s.W9[k]);
            U   = fma2(T[k],  w, U);
            UX  = fma2(X[k],  w, UX);
            UT  = fma2(Tt[k], w, UT);
            UXX = fma2(XX[k], w, UXX);
        }

        const float nu = 0.0031830988618379067f;   // 0.01 / pi
        u64 NEGNU = pk2(-nu, -nu);
        u64 F = fma2(U, UX, fma2(NEGNU, UXX, UT)); // u_t + u*u_x - nu*u_xx

        float u0, u1;    upk2(U, u0, u1);
        float ux0, ux1;  upk2(UX, ux0, ux1);
        float uxx0, uxx1; upk2(UXX, uxx0, uxx1);
        float f0, f1;    upk2(F, f0, f1);

        int offF = nf + n0 + 2 * nb;
        if (i0 < nf) {
            out[i0]               = u0;
            out[offF + i0]        = f0;
            out[offF + nf + i0]   = ux0;
            out[offF + 2*nf + i0] = uxx0;
        }
        if (i1 < nf) {
            out[i1]               = u1;
            out[offF + i1]        = f1;
            out[offF + nf + i1]   = ux1;
            out[offF + 2*nf + i1] = uxx1;
        }
    }
}

// ---------------------------------------------------------------------------
// Output layout (reference tuple order, concatenated):
//   [0, nf) u_pred_f | [nf, +n0) u_pred_0 | [+nb) left | [+nb) right
//   | [+nf) f | [+nf) u_x | [+nf) u_xx
// ---------------------------------------------------------------------------
extern "C" void kernel_launch(void* const* d_in, const int* in_sizes, int n_in,
                              void* d_out, int out_size)
{
    Params p;
    for (int i = 0; i < 9; i++) {
        p.W[i] = (const float*)d_in[4 + 2 * i];
        p.b[i] = (const float*)d_in[5 + 2 * i];
    }
    const float* Xf = (const float*)d_in[0];
    const float* x0 = (const float*)d_in[1];
    const float* xl = (const float*)d_in[2];
    const float* xr = (const float*)d_in[3];

    int nf = in_sizes[0] / 2;
    int n0 = in_sizes[1] / 2;
    int nb = in_sizes[2] / 2;

    float* out = (float*)d_out;

    int nfBlocks  = (nf + 255) / 256;
    int fwdBlocks = (n0 + 2 * nb + 127) / 128;
    int totalVB   = nfBlocks + fwdBlocks;

    // One full wave: 152 SMs (GB300) x 3 blocks/SM.
    int grid = 152 * 3;
    if (grid > totalVB) grid = totalVB;

    reset_kernel<<<1, 1>>>();
    fused_kernel<<<grid, 128>>>(Xf, x0, xl, xr, p, out, nf, n0, nb);
}

// round 14
// speedup vs baseline: 1.5178x; 1.0797x over previous
#include <cuda_runtime.h>

typedef unsigned long long u64;

#define HID 10

struct Params {
    const float* W[9];
    const float* b[9];
};

// Weight bank layout: weights duplicated into (w,w) float2 so one constant
// load feeds a packed-across-points f32x2 FMA.
struct __align__(16) CW {
    float2 Wh[7][HID][HID];   // layers 2..8 (10 -> 10), duplicated
    float2 bh2[7][HID];       // (b, b) pre-packed (both points share bias)
    float2 W1[2][HID];        // layer 1 (2 -> 10), duplicated
    float2 W9[HID];           // layer 9 (10 -> 1), duplicated
    float2 b9_2;              // (b9, b9)
    float  b1[HID];
    float  b9;
};

__constant__ CW c_s;          // read path: constant port (no LDS, no GPR staging)
__device__ CW g_stage;        // staging buffer filled by prep_kernel
__device__ unsigned int g_vb_counter;

__device__ __forceinline__ u64 pk2(float lo, float hi) {
    u64 r; asm("mov.b64 %0,{%1,%2};" : "=l"(r) : "f"(lo), "f"(hi)); return r;
}
__device__ __forceinline__ void upk2(u64 v, float& lo, float& hi) {
    asm("mov.b64 {%0,%1},%2;" : "=f"(lo), "=f"(hi) : "l"(v));
}
__device__ __forceinline__ u64 fma2(u64 a, u64 b, u64 c) {
    u64 d; asm("fma.rn.f32x2 %0,%1,%2,%3;" : "=l"(d) : "l"(a), "l"(b), "l"(c)); return d;
}
__device__ __forceinline__ u64 mul2(u64 a, u64 b) {
    u64 d; asm("mul.rn.f32x2 %0,%1,%2;" : "=l"(d) : "l"(a), "l"(b)); return d;
}

// Single-instruction MUFU tanh (sm_90+): 1 op, ~16 cyc, no fma-pipe cost.
__device__ __forceinline__ float tanh_fast(float z) {
    float t;
    asm("tanh.approx.f32 %0, %1;" : "=f"(t) : "f"(z));
    return t;
}

// Prep: pack duplicated weight layout into g_stage and reset the counter.
__global__ void prep_kernel(Params p) {
    int t = threadIdx.x;
    if (t == 0) g_vb_counter = 0;
    for (int l = 0; l < 7; l++)
        for (int i = t; i < HID * HID; i += blockDim.x) {
            float w = p.W[l + 1][i];
            g_stage.Wh[l][i / HID][i % HID] = make_float2(w, w);
        }
    for (int l = 0; l < 7; l++)
        for (int i = t; i < HID; i += blockDim.x) {
            float b = p.b[l + 1][i];
            g_stage.bh2[l][i] = make_float2(b, b);
        }
    for (int i = t; i < 2 * HID; i += blockDim.x) {
        float w = p.W[0][i];
        g_stage.W1[i / HID][i % HID] = make_float2(w, w);
    }
    for (int i = t; i < HID; i += blockDim.x) {
        float w = p.W[8][i];
        g_stage.W9[i] = make_float2(w, w);
    }
    for (int i = t; i < HID; i += blockDim.x) g_stage.b1[i] = p.b[0][i];
    if (t == 0) {
        float b9 = p.b[8][0];
        g_stage.b9   = b9;
        g_stage.b9_2 = make_float2(b9, b9);
    }
}

// ---------------------------------------------------------------------------
// Persistent fused kernel with dynamic work-stealing over virtual blocks.
// Weights come from __constant__ memory (uniform across the warp; constant
// port, zero shared-memory traffic, zero GPR load-staging pressure).
//   vb in [0, nfBlocks): jet path, 2 points/thread, across-point f32x2
//     packing of all four jet components (T, X, Tt, XX).
//   vb in [nfBlocks, totalVB): forward-only path, 128 points per vb.
// ---------------------------------------------------------------------------
__global__ void __launch_bounds__(128, 3)
fused_kernel(const float* __restrict__ Xf,
             const float* __restrict__ p0, const float* __restrict__ p1,
             const float* __restrict__ p2,
             float* __restrict__ out,
             int nf, int n0, int nb)
{
    __shared__ int s_vb;

    const int nfBlocks = (nf + 255) >> 8;
    const int total    = n0 + 2 * nb;
    const int totalVB  = nfBlocks + ((total + 127) >> 7);

    const u64 ONE  = pk2(1.0f, 1.0f);
    const u64 NEG1 = pk2(-1.0f, -1.0f);
    const u64 NEG2 = pk2(-2.0f, -2.0f);

    for (;;) {
        if (threadIdx.x == 0)
            s_vb = (int)atomicAdd(&g_vb_counter, 1u);
        __syncthreads();
        int vb = s_vb;
        if (vb >= totalVB) break;
        __syncthreads();   // protect s_vb before next overwrite

        if (vb >= nfBlocks) {
            // ---------------- forward-only path ----------------
            int i = (vb - nfBlocks) * 128 + threadIdx.x;
            if (i >= total) continue;

            const float* src;
            int loc, off;
            if (i < n0)           { src = p0; loc = i;           off = nf; }
            else if (i < n0 + nb) { src = p1; loc = i - n0;      off = nf + n0; }
            else                  { src = p2; loc = i - n0 - nb; off = nf + n0 + nb; }

            float x  = src[2 * loc + 0];
            float tt = src[2 * loc + 1];

            float h[HID];
            #pragma unroll
            for (int j = 0; j < HID; j++)
                h[j] = tanh_fast(fmaf(x, c_s.W1[0][j].x, fmaf(tt, c_s.W1[1][j].x, c_s.b1[j])));

            #pragma unroll 1
            for (int l = 0; l < 7; l++) {
                float z[HID];
                #pragma unroll
                for (int j = 0; j < HID; j++) z[j] = c_s.bh2[l][j].x;
                #pragma unroll
                for (int k = 0; k < HID; k++) {
                    float hk = h[k];
                    #pragma unroll
                    for (int j = 0; j < HID; j++)
                        z[j] = fmaf(hk, c_s.Wh[l][k][j].x, z[j]);
                }
                #pragma unroll
                for (int j = 0; j < HID; j++) h[j] = tanh_fast(z[j]);
            }

            float u = c_s.b9;
            #pragma unroll
            for (int k = 0; k < HID; k++) u = fmaf(h[k], c_s.W9[k].x, u);

            out[off + loc] = u;
            continue;
        }

        // ---------------- jet path: 2 points per thread ----------------
        int i0 = vb * 256 + threadIdx.x;
        int i1 = i0 + 128;
        int c0 = min(i0, nf - 1);
        int c1 = min(i1, nf - 1);

        float2 xy0 = reinterpret_cast<const float2*>(Xf)[c0];
        float2 xy1 = reinterpret_cast<const float2*>(Xf)[c1];

        // Packed-across-points jet state.
        u64 T[HID], X[HID], Tt[HID], XX[HID];

        // Layer 1: z = w0*x + w1*t + b; zx = w0, zt = w1, zxx = 0.
        #pragma unroll
        for (int j = 0; j < HID; j++) {
            float w0 = c_s.W1[0][j].x;
            float w1 = c_s.W1[1][j].x;
            float b  = c_s.b1[j];
            float z0 = fmaf(xy0.x, w0, fmaf(xy0.y, w1, b));
            float z1 = fmaf(xy1.x, w0, fmaf(xy1.y, w1, b));
            u64 Tn  = pk2(tanh_fast(z0), tanh_fast(z1));
            u64 T2  = mul2(Tn, Tn);
            u64 SV  = fma2(T2, NEG1, ONE);              // 1 - t^2
            u64 W0d = *reinterpret_cast<const u64*>(&c_s.W1[0][j]);
            u64 W1d = *reinterpret_cast<const u64*>(&c_s.W1[1][j]);
            u64 W02 = mul2(W0d, W0d);                   // zx^2
            u64 G   = mul2(Tn, W02);
            u64 H   = mul2(G, NEG2);                    // -2 t zx^2  (zxx=0)
            T[j]  = Tn;
            X[j]  = mul2(SV, W0d);
            Tt[j] = mul2(SV, W1d);
            XX[j] = mul2(SV, H);
        }

        // Hidden layers 2..8
        #pragma unroll 1
        for (int l = 0; l < 7; l++) {
            u64 Z[HID], ZX[HID], ZT[HID], ZXX[HID];
            #pragma unroll
            for (int j = 0; j < HID; j++) {
                Z[j]   = *reinterpret_cast<const u64*>(&c_s.bh2[l][j]);  // (b,b)
                ZX[j]  = 0ull;
                ZT[j]  = 0ull;
                ZXX[j] = 0ull;
            }
            #pragma unroll
            for (int k = 0; k < HID; k++) {
                u64 Tk = T[k], Xk = X[k], Ttk = Tt[k], XXk = XX[k];
                #pragma unroll
                for (int j = 0; j < HID; j++) {
                    u64 w = *reinterpret_cast<const u64*>(&c_s.Wh[l][k][j]);
                    Z[j]   = fma2(Tk,  w, Z[j]);
                    ZX[j]  = fma2(Xk,  w, ZX[j]);
                    ZT[j]  = fma2(Ttk, w, ZT[j]);
                    ZXX[j] = fma2(XXk, w, ZXX[j]);
                }
            }
            #pragma unroll
            for (int j = 0; j < HID; j++) {
                float z0, z1;  upk2(Z[j], z0, z1);
                u64 Tn  = pk2(tanh_fast(z0), tanh_fast(z1));
                u64 T2  = mul2(Tn, Tn);
                u64 SV  = fma2(T2, NEG1, ONE);          // 1 - t^2
                u64 ZX2 = mul2(ZX[j], ZX[j]);
                u64 G   = mul2(Tn, ZX2);
                u64 H   = fma2(G, NEG2, ZXX[j]);        // zxx - 2 t zx^2
                T[j]  = Tn;
                XX[j] = mul2(SV, H);
                X[j]  = mul2(SV, ZX[j]);
                Tt[j] = mul2(SV, ZT[j]);
            }
        }

        // Output layer (10 -> 1), linear; fully packed.
        u64 U   = *reinterpret_cast<const u64*>(&c_s.b9_2);
        u64 UX  = 0ull, UT = 0ull, UXX = 0ull;
        #pragma unroll
        for (int k = 0; k < HID; k++) {
            u64 w = *reinterpret_cast<const u64*>(&c_s.W9[k]);
            U   = fma2(T[k],  w, U);
            UX  = fma2(X[k],  w, UX);
            UT  = fma2(Tt[k], w, UT);
            UXX = fma2(XX[k], w, UXX);
        }

        const float nu = 0.0031830988618379067f;   // 0.01 / pi
        u64 NEGNU = pk2(-nu, -nu);
        u64 F = fma2(U, UX, fma2(NEGNU, UXX, UT)); // u_t + u*u_x - nu*u_xx

        float u0, u1;     upk2(U, u0, u1);
        float ux0, ux1;   upk2(UX, ux0, ux1);
        float uxx0, uxx1; upk2(UXX, uxx0, uxx1);
        float f0, f1;     upk2(F, f0, f1);

        int offF = nf + n0 + 2 * nb;
        if (i0 < nf) {
            out[i0]               = u0;
            out[offF + i0]        = f0;
            out[offF + nf + i0]   = ux0;
            out[offF + 2*nf + i0] = uxx0;
        }
        if (i1 < nf) {
            out[i1]               = u1;
            out[offF + i1]        = f1;
            out[offF + nf + i1]   = ux1;
            out[offF + 2*nf + i1] = uxx1;
        }
    }
}

// ---------------------------------------------------------------------------
// Output layout (reference tuple order, concatenated):
//   [0, nf) u_pred_f | [nf, +n0) u_pred_0 | [+nb) left | [+nb) right
//   | [+nf) f | [+nf) u_x | [+nf) u_xx
// ---------------------------------------------------------------------------
extern "C" void kernel_launch(void* const* d_in, const int* in_sizes, int n_in,
                              void* d_out, int out_size)
{
    Params p;
    for (int i = 0; i < 9; i++) {
        p.W[i] = (const float*)d_in[4 + 2 * i];
        p.b[i] = (const float*)d_in[5 + 2 * i];
    }
    const float* Xf = (const float*)d_in[0];
    const float* x0 = (const float*)d_in[1];
    const float* xl = (const float*)d_in[2];
    const float* xr = (const float*)d_in[3];

    int nf = in_sizes[0] / 2;
    int n0 = in_sizes[1] / 2;
    int nb = in_sizes[2] / 2;

    float* out = (float*)d_out;

    int nfBlocks  = (nf + 255) / 256;
    int fwdBlocks = (n0 + 2 * nb + 127) / 128;
    int totalVB   = nfBlocks + fwdBlocks;

    // One full wave: 152 SMs (GB300) x 3 blocks/SM.
    int grid = 152 * 3;
    if (grid > totalVB) grid = totalVB;

    // 1) pack weights into staging + reset counter, 2) D2D copy into the
    //    constant bank (graph-capturable memcpy node), 3) main kernel.
    prep_kernel<<<1, 128>>>(p);
    void* stage_ptr = nullptr;
    cudaGetSymbolAddress(&stage_ptr, g_stage);
    cudaMemcpyToSymbolAsync(c_s, stage_ptr, sizeof(CW), 0,
                            cudaMemcpyDeviceToDevice, 0);
    fused_kernel<<<grid, 128>>>(Xf, x0, xl, xr, out, nf, n0, nb);
}